// round 15
// baseline (speedup 1.0000x reference)
#include <cuda_runtime.h>
#include <cuda_fp16.h>
#include <cstdint>
#include <cstddef>

#define FD 32
#define HD 64
#define ED 128
#define MT 128
#define TPC 8

#define N_MAX    1600000
#define NSEG_MAX 65536

__device__ int g_count[NSEG_MAX];
__device__ int g_cursor[NSEG_MAX];
__device__ int g_sorted[N_MAX];

// ---------------- smem layout (bytes) ----------------
//   X  : 2 x [128 m][k<32] stride 80B (fp16, double-buffered)
//   B1 : [64 n][k<32]   stride 80B   (W1^T fp16)
//   B2 : [128 n][k<64]  stride 144B  (W2^T fp16)
#define XS   80
#define HS   144
#define B1S  80
#define XBUF 10240
#define OFF_X    0
#define OFF_B1   20480
#define OFF_B2   25600
#define OFF_SB1  44032
#define OFF_SB2  44288
#define SMEM_TOTAL 44800

__device__ __forceinline__ uint32_t smem_u32_of(const void* p) {
    uint32_t a;
    asm("{ .reg .u64 t; cvta.to.shared.u64 t, %1; cvt.u32.u64 %0, t; }" : "=r"(a) : "l"(p));
    return a;
}
__device__ __forceinline__ void ldsm4(uint32_t* r, uint32_t a) {
    asm volatile("ldmatrix.sync.aligned.m8n8.x4.shared.b16 {%0,%1,%2,%3}, [%4];"
                 : "=r"(r[0]), "=r"(r[1]), "=r"(r[2]), "=r"(r[3]) : "r"(a));
}
__device__ __forceinline__ void mma16816(float* c, const uint32_t* a, uint32_t b0, uint32_t b1) {
    asm volatile("mma.sync.aligned.m16n8k16.row.col.f32.f16.f16.f32 "
                 "{%0,%1,%2,%3}, {%4,%5,%6,%7}, {%8,%9}, {%0,%1,%2,%3};"
                 : "+f"(c[0]), "+f"(c[1]), "+f"(c[2]), "+f"(c[3])
                 : "r"(a[0]), "r"(a[1]), "r"(a[2]), "r"(a[3]), "r"(b0), "r"(b1));
}
__device__ __forceinline__ void sts128(uint32_t a, uint32_t x, uint32_t y, uint32_t z, uint32_t w) {
    asm volatile("st.shared.v4.b32 [%0], {%1,%2,%3,%4};" :: "r"(a), "r"(x), "r"(y), "r"(z), "r"(w) : "memory");
}
__device__ __forceinline__ uint32_t pack2(float v0, float v1) {
    __half2 h = __floats2half2_rn(v0, v1);
    return *reinterpret_cast<uint32_t*>(&h);
}

// ---------------- sort pipeline ----------------

__global__ void zero_and_init(float* __restrict__ out, int out_n, int nseg) {
    int i = blockIdx.x * blockDim.x + threadIdx.x;
    if (i < out_n) out[i] = 0.0f;          // 0-init == isfinite guard for ReLU>=0 maxima
    if (i < nseg) g_count[i] = 0;
}
// ILP-4 histogram: int4 loads, 4 independent atomics per thread
__global__ void hist_kernel(const int* __restrict__ seg, int n) {
    int i = blockIdx.x * blockDim.x + threadIdx.x;
    int b = i * 4;
    if (b + 3 < n) {
        int4 s = *reinterpret_cast<const int4*>(seg + b);
        atomicAdd(&g_count[s.x], 1);
        atomicAdd(&g_count[s.y], 1);
        atomicAdd(&g_count[s.z], 1);
        atomicAdd(&g_count[s.w], 1);
    } else {
        for (int k = b; k < n; k++) atomicAdd(&g_count[seg[k]], 1);
    }
}
__global__ __launch_bounds__(1024) void scan_kernel(int nseg) {
    __shared__ int ssum[1024];
    int t = threadIdx.x;
    int C = (nseg + 1023) >> 10;
    int lo = t * C, hi = min(lo + C, nseg);
    int s = 0;
    for (int i = lo; i < hi; i++) s += g_count[i];
    ssum[t] = s;
    __syncthreads();
    for (int d = 1; d < 1024; d <<= 1) {
        int o = (t >= d) ? ssum[t - d] : 0;
        __syncthreads();
        ssum[t] += o;
        __syncthreads();
    }
    int pre = ssum[t] - s;
    for (int i = lo; i < hi; i++) { int c = g_count[i]; g_cursor[i] = pre; pre += c; }
}
// ILP-4 scatter
__global__ void scatter_kernel(const int* __restrict__ seg, int n) {
    int i = blockIdx.x * blockDim.x + threadIdx.x;
    int b = i * 4;
    if (b + 3 < n) {
        int4 s = *reinterpret_cast<const int4*>(seg + b);
        int p0 = atomicAdd(&g_cursor[s.x], 1);
        int p1 = atomicAdd(&g_cursor[s.y], 1);
        int p2 = atomicAdd(&g_cursor[s.z], 1);
        int p3 = atomicAdd(&g_cursor[s.w], 1);
        g_sorted[p0] = b;
        g_sorted[p1] = b + 1;
        g_sorted[p2] = b + 2;
        g_sorted[p3] = b + 3;
    } else {
        for (int k = b; k < n; k++) {
            int pos = atomicAdd(&g_cursor[seg[k]], 1);
            g_sorted[pos] = k;
        }
    }
}

// ---------------- warp-MMA fused MLP + fragment-space segment max ----------------

__global__ __launch_bounds__(256, 2) void fused_mlp_segmax_mma(
    const float* __restrict__ X, const int* __restrict__ seg,
    const float* __restrict__ W1, const float* __restrict__ b1,
    const float* __restrict__ W2, const float* __restrict__ b2,
    unsigned* __restrict__ out, int n)
{
    extern __shared__ char smem[];
    const uint32_t su = smem_u32_of(smem);
    int t = threadIdx.x;
    int wid = t >> 5, lane = t & 31;
    int g = lane >> 2, tig = lane & 3;
    int m0 = wid * 16;

    float* sb1 = (float*)(smem + OFF_SB1);
    float* sb2 = (float*)(smem + OFF_SB2);

    // ---- stage fp16 weights, coalesced (lanes walk n) ----
    #pragma unroll
    for (int i = 0; i < 8; i++) {                 // B1: 64n x 32k
        int e = i * 256 + t, nn = e & 63, k = e >> 6;
        *(__half*)(smem + OFF_B1 + nn * B1S + k * 2) = __float2half_rn(W1[k * HD + nn]);
    }
    #pragma unroll
    for (int i = 0; i < 32; i++) {                // B2: 128n x 64k
        int e = i * 256 + t, nn = e & 127, k = e >> 7;
        *(__half*)(smem + OFF_B2 + nn * HS + k * 2) = __float2half_rn(W2[k * ED + nn]);
    }
    if (t < HD) sb1[t] = b1[t];
    if (t < ED) sb2[t] = b2[t];
    __syncthreads();   // the only block barrier

    int a_row = lane & 15;
    int a_koff = (lane >> 4) * 16;
    int b_nrow = (lane & 7) + ((lane >> 4) << 3);
    int b_koff = ((lane >> 3) & 1) * 16;

    int tiles_total = (n + MT - 1) >> 7;
    int mrow = t >> 1, half = t & 1;              // staging assignment (2 thr/row)

    // ---- initial gather prefetch (tile 0) + stage into buffer 0 ----
    float4 xv[4];
    int pseg = 0;
    {
        int tile0 = blockIdx.x * TPC;
        if (tile0 < tiles_total) {
            int base0 = tile0 << 7;
            int p = g_sorted[min(base0 + mrow, n - 1)];
            const float4* xr = reinterpret_cast<const float4*>(X + (size_t)p * FD) + half * 4;
            #pragma unroll
            for (int i = 0; i < 4; i++) xv[i] = __ldg(xr + i);
            int ps = g_sorted[min(base0 + m0 + lane, n - 1)];
            pseg = __ldg(seg + ps);
        }
    }
    {
        uint32_t w[8];
        #pragma unroll
        for (int i = 0; i < 4; i++) {
            w[2 * i]     = pack2(xv[i].x, xv[i].y);
            w[2 * i + 1] = pack2(xv[i].z, xv[i].w);
        }
        uint32_t o0 = su + OFF_X + (uint32_t)(mrow * XS + half * 32);
        sts128(o0,      w[0], w[1], w[2], w[3]);
        sts128(o0 + 16, w[4], w[5], w[6], w[7]);
    }

    for (int it = 0; it < TPC; it++) {
        int tile = blockIdx.x * TPC + it;
        if (tile >= tiles_total) break;
        uint32_t xb  = su + OFF_X + (uint32_t)((it & 1) * XBUF);        // current
        uint32_t xbn = su + OFF_X + (uint32_t)(((it + 1) & 1) * XBUF);  // next

        // ---- this tile's seg ids in registers; run-boundary mask ----
        int segv = pseg;                           // lane l (<16): seg of row m0+l
        int prev = __shfl_up_sync(0xffffffffu, segv, 1);
        unsigned bmask = __ballot_sync(0xffffffffu,
                                       (lane > 0) && (lane < 16) && (segv != prev));

        // ---- issue next tile's gather (hidden under GEMMs + epilogue) ----
        {
            int tile1 = tile + 1;
            bool more = (it + 1 < TPC) && (tile1 < tiles_total);
            int base1 = tile1 << 7;
            int ip = more ? min(base1 + mrow, n - 1) : 0;
            int p = g_sorted[ip];
            const float4* xr = reinterpret_cast<const float4*>(X + (size_t)p * FD) + half * 4;
            #pragma unroll
            for (int i = 0; i < 4; i++) xv[i] = __ldg(xr + i);
            int is = more ? min(base1 + m0 + lane, n - 1) : 0;
            int ps = g_sorted[is];
            pseg = __ldg(seg + ps);
        }
        __syncwarp();   // current buffer's STS (from previous iter) visible

        // ================ GEMM1: H = relu(X @ W1 + b1), 16m x 64n ================
        float acc1[8][4];
        #pragma unroll
        for (int nt = 0; nt < 8; nt++)
            #pragma unroll
            for (int c = 0; c < 4; c++) acc1[nt][c] = 0.f;

        #pragma unroll
        for (int ks = 0; ks < 2; ks++) {
            uint32_t ah[4];
            ldsm4(ah, xb + (uint32_t)((m0 + a_row) * XS + ks * 32 + a_koff));
            #pragma unroll
            for (int ntp = 0; ntp < 4; ntp++) {
                uint32_t bh[4];
                ldsm4(bh, su + (uint32_t)(OFF_B1 + (16 * ntp + b_nrow) * B1S + ks * 32 + b_koff));
                mma16816(acc1[2 * ntp],     ah, bh[0], bh[1]);
                mma16816(acc1[2 * ntp + 1], ah, bh[2], bh[3]);
            }
        }

        // ---- H: bias+ReLU+fp16 in registers; GEMM1 C-frags == GEMM2 A-frags ----
        uint32_t Ah[4][4];
        #pragma unroll
        for (int kb = 0; kb < 4; kb++) {
            #pragma unroll
            for (int h = 0; h < 2; h++) {
                int nt = 2 * kb + h;
                int j = 8 * nt + 2 * tig;
                float bb0 = sb1[j], bb1 = sb1[j + 1];
                Ah[kb][2 * h] =
                    pack2(fmaxf(acc1[nt][0] + bb0, 0.f), fmaxf(acc1[nt][1] + bb1, 0.f));
                Ah[kb][2 * h + 1] =
                    pack2(fmaxf(acc1[nt][2] + bb0, 0.f), fmaxf(acc1[nt][3] + bb1, 0.f));
            }
        }

        // ================ GEMM2 (two 64-col halves) + fragment-space epilogue ================
        #pragma unroll 1
        for (int nh = 0; nh < 2; nh++) {
            float acc[8][4];
            #pragma unroll
            for (int nt = 0; nt < 8; nt++)
                #pragma unroll
                for (int c = 0; c < 4; c++) acc[nt][c] = 0.f;

            #pragma unroll
            for (int ks = 0; ks < 4; ks++)
                #pragma unroll
                for (int ntp = 0; ntp < 4; ntp++) {
                    uint32_t bh[4];
                    ldsm4(bh, su + (uint32_t)(OFF_B2 + (64 * nh + 16 * ntp + b_nrow) * HS + ks * 32 + b_koff));
                    mma16816(acc[2 * ntp],     Ah[ks], bh[0], bh[1]);
                    mma16816(acc[2 * ntp + 1], Ah[ks], bh[2], bh[3]);
                }

            // After nh=0's MMAs: stage NEXT tile's X into the alternate buffer.
            // Prefetch LDGs have had all of GEMM1+GEMM2(nh=0) to complete; the
            // STS→LDSM latency is covered by nh=1's GEMM + both epilogues.
            if (nh == 0) {
                uint32_t w[8];
                #pragma unroll
                for (int i = 0; i < 4; i++) {
                    w[2 * i]     = pack2(xv[i].x, xv[i].y);
                    w[2 * i + 1] = pack2(xv[i].z, xv[i].w);
                }
                uint32_t o0 = xbn + (uint32_t)(mrow * XS + half * 32);
                sts128(o0,      w[0], w[1], w[2], w[3]);
                sts128(o0 + 16, w[4], w[5], w[6], w[7]);
            }

            // bias + ReLU in place
            #pragma unroll
            for (int nt = 0; nt < 8; nt++) {
                int j = 64 * nh + 8 * nt + 2 * tig;
                float bb0 = sb2[j], bb1 = sb2[j + 1];
                acc[nt][0] = fmaxf(acc[nt][0] + bb0, 0.f);
                acc[nt][1] = fmaxf(acc[nt][1] + bb1, 0.f);
                acc[nt][2] = fmaxf(acc[nt][2] + bb0, 0.f);
                acc[nt][3] = fmaxf(acc[nt][3] + bb1, 0.f);
            }

            // per-run shuffle-butterfly max over rows, atomics from lane g==nt
            int start = 0;
            while (start < 16) {
                unsigned hi = bmask & (0xFFFFFFFFu << (start + 1));
                int nb = hi ? (__ffs(hi) - 1) : 16;
                int rseg = __shfl_sync(0xffffffffu, segv, start);
                bool inLo = (g >= start) && (g < nb);         // row m0+g
                bool inHi = (g + 8 >= start) && (g + 8 < nb); // row m0+g+8
                float va0 = 0.f, va1 = 0.f;
                #pragma unroll
                for (int nt = 0; nt < 8; nt++) {
                    float a0 = fmaxf(inLo ? acc[nt][0] : 0.f, inHi ? acc[nt][2] : 0.f);
                    float a1 = fmaxf(inLo ? acc[nt][1] : 0.f, inHi ? acc[nt][3] : 0.f);
                    a0 = fmaxf(a0, __shfl_xor_sync(0xffffffffu, a0, 4));
                    a1 = fmaxf(a1, __shfl_xor_sync(0xffffffffu, a1, 4));
                    a0 = fmaxf(a0, __shfl_xor_sync(0xffffffffu, a0, 8));
                    a1 = fmaxf(a1, __shfl_xor_sync(0xffffffffu, a1, 8));
                    a0 = fmaxf(a0, __shfl_xor_sync(0xffffffffu, a0, 16));
                    a1 = fmaxf(a1, __shfl_xor_sync(0xffffffffu, a1, 16));
                    if (g == nt) { va0 = a0; va1 = a1; }
                }
                unsigned* ob = out + (size_t)rseg * ED + 64 * nh + 8 * g + 2 * tig;
                unsigned u0 = __float_as_uint(va0);   // >=0: bit order == fp order
                unsigned u1 = __float_as_uint(va1);
                if (u0) atomicMax(ob, u0);
                if (u1) atomicMax(ob + 1, u1);
                start = nb;
            }
        }
    }
}

extern "C" void kernel_launch(void* const* d_in, const int* in_sizes, int n_in,
                              void* d_out, int out_size)
{
    const float* X   = (const float*)d_in[0];
    const int*   seg = (const int*)  d_in[1];
    const float* W1  = (const float*)d_in[2];
    const float* b1  = (const float*)d_in[3];
    const float* W2  = (const float*)d_in[4];
    const float* b2  = (const float*)d_in[5];
    float* out = (float*)d_out;

    int n = in_sizes[1];
    int nseg = out_size / ED;

    cudaFuncSetAttribute(fused_mlp_segmax_mma,
                         cudaFuncAttributeMaxDynamicSharedMemorySize, SMEM_TOTAL);

    int initN = max(out_size, nseg);
    zero_and_init<<<(initN + 255) / 256, 256>>>(out, out_size, nseg);
    int q = (n + 3) / 4;
    hist_kernel<<<(q + 255) / 256, 256>>>(seg, n);
    scan_kernel<<<1, 1024>>>(nseg);
    scatter_kernel<<<(q + 255) / 256, 256>>>(seg, n);

    int tiles = (n + MT - 1) / MT;
    int grid = (tiles + TPC - 1) / TPC;
    fused_mlp_segmax_mma<<<grid, 256, SMEM_TOTAL>>>(X, seg, W1, b1, W2, b2, (unsigned*)out, n);
}

// round 16
// speedup vs baseline: 1.0302x; 1.0302x over previous
#include <cuda_runtime.h>
#include <cuda_fp16.h>
#include <cstdint>
#include <cstddef>

#define FD 32
#define HD 64
#define ED 128
#define MT 128

#define N_MAX    1600000
#define NSEG_MAX 65536

__device__ int g_count[NSEG_MAX];
__device__ int g_cursor[NSEG_MAX];
__device__ int g_sorted[N_MAX];

// ---------------- smem layout (bytes) ----------------
//   X  : [128 m][k<32]  stride 80B   (fp16)
//   B1 : [64 n][k<32]   stride 80B   (W1^T fp16)
//   B2 : [128 n][k<64]  stride 144B  (W2^T fp16)
#define XS   80
#define HS   144
#define B1S  80
#define OFF_X    0
#define OFF_B1   10240
#define OFF_B2   15360
#define OFF_SB1  33792
#define OFF_SB2  34048
#define SMEM_TOTAL 34560

__device__ __forceinline__ uint32_t smem_u32_of(const void* p) {
    uint32_t a;
    asm("{ .reg .u64 t; cvta.to.shared.u64 t, %1; cvt.u32.u64 %0, t; }" : "=r"(a) : "l"(p));
    return a;
}
__device__ __forceinline__ void ldsm4(uint32_t* r, uint32_t a) {
    asm volatile("ldmatrix.sync.aligned.m8n8.x4.shared.b16 {%0,%1,%2,%3}, [%4];"
                 : "=r"(r[0]), "=r"(r[1]), "=r"(r[2]), "=r"(r[3]) : "r"(a));
}
__device__ __forceinline__ void mma16816(float* c, const uint32_t* a, uint32_t b0, uint32_t b1) {
    asm volatile("mma.sync.aligned.m16n8k16.row.col.f32.f16.f16.f32 "
                 "{%0,%1,%2,%3}, {%4,%5,%6,%7}, {%8,%9}, {%0,%1,%2,%3};"
                 : "+f"(c[0]), "+f"(c[1]), "+f"(c[2]), "+f"(c[3])
                 : "r"(a[0]), "r"(a[1]), "r"(a[2]), "r"(a[3]), "r"(b0), "r"(b1));
}
__device__ __forceinline__ void sts128(uint32_t a, uint32_t x, uint32_t y, uint32_t z, uint32_t w) {
    asm volatile("st.shared.v4.b32 [%0], {%1,%2,%3,%4};" :: "r"(a), "r"(x), "r"(y), "r"(z), "r"(w) : "memory");
}
__device__ __forceinline__ uint32_t pack2(float v0, float v1) {
    __half2 h = __floats2half2_rn(v0, v1);
    return *reinterpret_cast<uint32_t*>(&h);
}

// ---------------- sort pipeline ----------------

__global__ void zero_and_init(float* __restrict__ out, int out_n, int nseg) {
    int i = blockIdx.x * blockDim.x + threadIdx.x;
    if (i < out_n) out[i] = 0.0f;          // 0-init == isfinite guard for ReLU>=0 maxima
    if (i < nseg) g_count[i] = 0;
}
__global__ void hist_kernel(const int* __restrict__ seg, int n) {
    int i = blockIdx.x * blockDim.x + threadIdx.x;
    if (i < n) atomicAdd(&g_count[seg[i]], 1);
}
__global__ __launch_bounds__(1024) void scan_kernel(int nseg) {
    __shared__ int ssum[1024];
    int t = threadIdx.x;
    int C = (nseg + 1023) >> 10;
    int lo = t * C, hi = min(lo + C, nseg);
    int s = 0;
    for (int i = lo; i < hi; i++) s += g_count[i];
    ssum[t] = s;
    __syncthreads();
    for (int d = 1; d < 1024; d <<= 1) {
        int o = (t >= d) ? ssum[t - d] : 0;
        __syncthreads();
        ssum[t] += o;
        __syncthreads();
    }
    int pre = ssum[t] - s;
    for (int i = lo; i < hi; i++) { int c = g_count[i]; g_cursor[i] = pre; pre += c; }
}
__global__ void scatter_kernel(const int* __restrict__ seg, int n) {
    int i = blockIdx.x * blockDim.x + threadIdx.x;
    if (i < n) { int pos = atomicAdd(&g_cursor[seg[i]], 1); g_sorted[pos] = i; }
}

// ---------------- persistent warp-MMA fused MLP + fragment-space segment max ----------------

__global__ __launch_bounds__(256, 2) void fused_mlp_segmax_mma(
    const float* __restrict__ X, const int* __restrict__ seg,
    const float* __restrict__ W1, const float* __restrict__ b1,
    const float* __restrict__ W2, const float* __restrict__ b2,
    unsigned* __restrict__ out, int n)
{
    extern __shared__ char smem[];
    const uint32_t su = smem_u32_of(smem);
    int t = threadIdx.x;
    int wid = t >> 5, lane = t & 31;
    int g = lane >> 2, tig = lane & 3;
    int m0 = wid * 16;

    float* sb1 = (float*)(smem + OFF_SB1);
    float* sb2 = (float*)(smem + OFF_SB2);

    // ---- stage fp16 weights once per (persistent) CTA ----
    #pragma unroll
    for (int i = 0; i < 8; i++) {                 // B1: 64n x 32k
        int e = i * 256 + t, nn = e & 63, k = e >> 6;
        *(__half*)(smem + OFF_B1 + nn * B1S + k * 2) = __float2half_rn(W1[k * HD + nn]);
    }
    #pragma unroll
    for (int i = 0; i < 32; i++) {                // B2: 128n x 64k
        int e = i * 256 + t, nn = e & 127, k = e >> 7;
        *(__half*)(smem + OFF_B2 + nn * HS + k * 2) = __float2half_rn(W2[k * ED + nn]);
    }
    if (t < HD) sb1[t] = b1[t];
    if (t < ED) sb2[t] = b2[t];
    __syncthreads();   // the only block barrier

    int a_row = lane & 15;
    int a_koff = (lane >> 4) * 16;
    int b_nrow = (lane & 7) + ((lane >> 4) << 3);
    int b_koff = ((lane >> 3) & 1) * 16;

    // ---- hoist tile-invariant B1 fragments into registers (32 regs) ----
    uint32_t B1f[2][4][4];
    #pragma unroll
    for (int ks = 0; ks < 2; ks++)
        #pragma unroll
        for (int ntp = 0; ntp < 4; ntp++)
            ldsm4(B1f[ks][ntp],
                  su + (uint32_t)(OFF_B1 + (16 * ntp + b_nrow) * B1S + ks * 32 + b_koff));

    int tiles_total = (n + MT - 1) >> 7;
    int stride = gridDim.x;
    int mrow = t >> 1, half = t & 1;              // staging assignment (2 thr/row)

    // ---- initial gather prefetch (first tile of this CTA) ----
    float4 xv[4];
    int pseg = 0;
    if (blockIdx.x < tiles_total) {
        int base0 = blockIdx.x << 7;
        int p = g_sorted[min(base0 + mrow, n - 1)];
        const float4* xr = reinterpret_cast<const float4*>(X + (size_t)p * FD) + half * 4;
        #pragma unroll
        for (int i = 0; i < 4; i++) xv[i] = __ldg(xr + i);
        int ps = g_sorted[min(base0 + m0 + lane, n - 1)];
        pseg = __ldg(seg + ps);
    }

    for (int tile = blockIdx.x; tile < tiles_total; tile += stride) {

        // ---- this tile's seg ids in registers; run-boundary mask ----
        int segv = pseg;                           // lane l (<16): seg of row m0+l
        int prev = __shfl_up_sync(0xffffffffu, segv, 1);
        unsigned bmask = __ballot_sync(0xffffffffu,
                                       (lane > 0) && (lane < 16) && (segv != prev));

        // ---- stage current tile X from prefetched registers ----
        {
            uint32_t w[8];
            #pragma unroll
            for (int i = 0; i < 4; i++) {
                w[2 * i]     = pack2(xv[i].x, xv[i].y);
                w[2 * i + 1] = pack2(xv[i].z, xv[i].w);
            }
            uint32_t o0 = su + OFF_X + (uint32_t)(mrow * XS + half * 32);
            sts128(o0,      w[0], w[1], w[2], w[3]);
            sts128(o0 + 16, w[4], w[5], w[6], w[7]);
        }

        // ---- issue next tile's gather (latency hidden under GEMMs + epilogue) ----
        {
            int tile1 = tile + stride;
            bool more = tile1 < tiles_total;
            int base1 = tile1 << 7;
            int ip = more ? min(base1 + mrow, n - 1) : 0;
            int p = g_sorted[ip];
            const float4* xr = reinterpret_cast<const float4*>(X + (size_t)p * FD) + half * 4;
            #pragma unroll
            for (int i = 0; i < 4; i++) xv[i] = __ldg(xr + i);
            int is = more ? min(base1 + m0 + lane, n - 1) : 0;
            int ps = g_sorted[is];
            pseg = __ldg(seg + ps);
        }
        __syncwarp();

        // ================ GEMM1: H = relu(X @ W1 + b1), 16m x 64n ================
        float acc1[8][4];
        #pragma unroll
        for (int nt = 0; nt < 8; nt++)
            #pragma unroll
            for (int c = 0; c < 4; c++) acc1[nt][c] = 0.f;

        #pragma unroll
        for (int ks = 0; ks < 2; ks++) {
            uint32_t ah[4];
            ldsm4(ah, su + (uint32_t)(OFF_X + (m0 + a_row) * XS + ks * 32 + a_koff));
            #pragma unroll
            for (int ntp = 0; ntp < 4; ntp++) {
                mma16816(acc1[2 * ntp],     ah, B1f[ks][ntp][0], B1f[ks][ntp][1]);
                mma16816(acc1[2 * ntp + 1], ah, B1f[ks][ntp][2], B1f[ks][ntp][3]);
            }
        }

        // ---- H: bias+ReLU+fp16 in registers; GEMM1 C-frags == GEMM2 A-frags ----
        uint32_t Ah[4][4];
        #pragma unroll
        for (int kb = 0; kb < 4; kb++) {
            #pragma unroll
            for (int h = 0; h < 2; h++) {
                int nt = 2 * kb + h;
                int j = 8 * nt + 2 * tig;
                float bb0 = sb1[j], bb1 = sb1[j + 1];
                Ah[kb][2 * h] =
                    pack2(fmaxf(acc1[nt][0] + bb0, 0.f), fmaxf(acc1[nt][1] + bb1, 0.f));
                Ah[kb][2 * h + 1] =
                    pack2(fmaxf(acc1[nt][2] + bb0, 0.f), fmaxf(acc1[nt][3] + bb1, 0.f));
            }
        }

        // ================ GEMM2 (two 64-col halves) + fragment-space epilogue ================
        #pragma unroll 1
        for (int nh = 0; nh < 2; nh++) {
            float acc[8][4];
            #pragma unroll
            for (int nt = 0; nt < 8; nt++)
                #pragma unroll
                for (int c = 0; c < 4; c++) acc[nt][c] = 0.f;

            #pragma unroll
            for (int ks = 0; ks < 4; ks++)
                #pragma unroll
                for (int ntp = 0; ntp < 4; ntp++) {
                    uint32_t bh[4];
                    ldsm4(bh, su + (uint32_t)(OFF_B2 + (64 * nh + 16 * ntp + b_nrow) * HS + ks * 32 + b_koff));
                    mma16816(acc[2 * ntp],     Ah[ks], bh[0], bh[1]);
                    mma16816(acc[2 * ntp + 1], Ah[ks], bh[2], bh[3]);
                }

            // bias + ReLU in place
            #pragma unroll
            for (int nt = 0; nt < 8; nt++) {
                int j = 64 * nh + 8 * nt + 2 * tig;
                float bb0 = sb2[j], bb1 = sb2[j + 1];
                acc[nt][0] = fmaxf(acc[nt][0] + bb0, 0.f);
                acc[nt][1] = fmaxf(acc[nt][1] + bb1, 0.f);
                acc[nt][2] = fmaxf(acc[nt][2] + bb0, 0.f);
                acc[nt][3] = fmaxf(acc[nt][3] + bb1, 0.f);
            }

            // per-run shuffle-butterfly max over rows, atomics from lane g==nt
            int start = 0;
            while (start < 16) {
                unsigned hi = bmask & (0xFFFFFFFFu << (start + 1));
                int nb = hi ? (__ffs(hi) - 1) : 16;
                int rseg = __shfl_sync(0xffffffffu, segv, start);
                bool inLo = (g >= start) && (g < nb);         // row m0+g
                bool inHi = (g + 8 >= start) && (g + 8 < nb); // row m0+g+8
                float va0 = 0.f, va1 = 0.f;
                #pragma unroll
                for (int nt = 0; nt < 8; nt++) {
                    float a0 = fmaxf(inLo ? acc[nt][0] : 0.f, inHi ? acc[nt][2] : 0.f);
                    float a1 = fmaxf(inLo ? acc[nt][1] : 0.f, inHi ? acc[nt][3] : 0.f);
                    a0 = fmaxf(a0, __shfl_xor_sync(0xffffffffu, a0, 4));
                    a1 = fmaxf(a1, __shfl_xor_sync(0xffffffffu, a1, 4));
                    a0 = fmaxf(a0, __shfl_xor_sync(0xffffffffu, a0, 8));
                    a1 = fmaxf(a1, __shfl_xor_sync(0xffffffffu, a1, 8));
                    a0 = fmaxf(a0, __shfl_xor_sync(0xffffffffu, a0, 16));
                    a1 = fmaxf(a1, __shfl_xor_sync(0xffffffffu, a1, 16));
                    if (g == nt) { va0 = a0; va1 = a1; }
                }
                unsigned* ob = out + (size_t)rseg * ED + 64 * nh + 8 * g + 2 * tig;
                unsigned u0 = __float_as_uint(va0);   // >=0: bit order == fp order
                unsigned u1 = __float_as_uint(va1);
                if (u0) atomicMax(ob, u0);
                if (u1) atomicMax(ob + 1, u1);
                start = nb;
            }
        }
        __syncwarp();   // X region quiesced before next tile restage
    }
}

extern "C" void kernel_launch(void* const* d_in, const int* in_sizes, int n_in,
                              void* d_out, int out_size)
{
    const float* X   = (const float*)d_in[0];
    const int*   seg = (const int*)  d_in[1];
    const float* W1  = (const float*)d_in[2];
    const float* b1  = (const float*)d_in[3];
    const float* W2  = (const float*)d_in[4];
    const float* b2  = (const float*)d_in[5];
    float* out = (float*)d_out;

    int n = in_sizes[1];
    int nseg = out_size / ED;

    cudaFuncSetAttribute(fused_mlp_segmax_mma,
                         cudaFuncAttributeMaxDynamicSharedMemorySize, SMEM_TOTAL);

    int initN = max(out_size, nseg);
    zero_and_init<<<(initN + 255) / 256, 256>>>(out, out_size, nseg);
    hist_kernel<<<(n + 255) / 256, 256>>>(seg, n);
    scan_kernel<<<1, 1024>>>(nseg);
    scatter_kernel<<<(n + 255) / 256, 256>>>(seg, n);

    int tiles = (n + MT - 1) / MT;
    int grid = min(296, tiles);                   // persistent: 2 CTAs x 148 SMs
    fused_mlp_segmax_mma<<<grid, 256, SMEM_TOTAL>>>(X, seg, W1, b1, W2, b2, (unsigned*)out, n);
}

// round 17
// speedup vs baseline: 1.1079x; 1.0755x over previous
#include <cuda_runtime.h>
#include <cuda_fp16.h>
#include <cstdint>
#include <cstddef>

#define FD 32
#define HD 64
#define ED 128
#define MT 128

#define N_MAX    1600000
#define NSEG_MAX 65536

__device__ int g_count[NSEG_MAX];
__device__ int g_cursor[NSEG_MAX];
__device__ int g_sorted[N_MAX];

// ---------------- smem layout (bytes) ----------------
//   B1 : [64 n][k<32]   stride 80B   (W1^T fp16)
//   B2 : [128 n][k<64]  stride 144B  (W2^T fp16)
// (X tile eliminated: A-fragments gathered directly into registers.
//  H eliminated: GEMM1 C-frags become GEMM2 A-frags in registers.)
#define HS   144
#define B1S  80
#define OFF_B1   0
#define OFF_B2   5120
#define OFF_SB1  23552
#define OFF_SB2  23808
#define SMEM_TOTAL 24320

__device__ __forceinline__ uint32_t smem_u32_of(const void* p) {
    uint32_t a;
    asm("{ .reg .u64 t; cvta.to.shared.u64 t, %1; cvt.u32.u64 %0, t; }" : "=r"(a) : "l"(p));
    return a;
}
__device__ __forceinline__ void ldsm4(uint32_t* r, uint32_t a) {
    asm volatile("ldmatrix.sync.aligned.m8n8.x4.shared.b16 {%0,%1,%2,%3}, [%4];"
                 : "=r"(r[0]), "=r"(r[1]), "=r"(r[2]), "=r"(r[3]) : "r"(a));
}
__device__ __forceinline__ void mma16816(float* c, const uint32_t* a, uint32_t b0, uint32_t b1) {
    asm volatile("mma.sync.aligned.m16n8k16.row.col.f32.f16.f16.f32 "
                 "{%0,%1,%2,%3}, {%4,%5,%6,%7}, {%8,%9}, {%0,%1,%2,%3};"
                 : "+f"(c[0]), "+f"(c[1]), "+f"(c[2]), "+f"(c[3])
                 : "r"(a[0]), "r"(a[1]), "r"(a[2]), "r"(a[3]), "r"(b0), "r"(b1));
}
__device__ __forceinline__ uint32_t pack2(float v0, float v1) {
    __half2 h = __floats2half2_rn(v0, v1);
    return *reinterpret_cast<uint32_t*>(&h);
}

// ---------------- sort pipeline ----------------

__global__ void init_counts(int nseg) {
    int i = blockIdx.x * blockDim.x + threadIdx.x;
    if (i < nseg) g_count[i] = 0;
}
// Histogram + fused output zeroing (zero-write rides under atomic latency).
// 0-init of out == isfinite guard for ReLU>=0 maxima.
__global__ void hist_zero_kernel(const int* __restrict__ seg, int n,
                                 float* __restrict__ out, int out_n) {
    int i = blockIdx.x * blockDim.x + threadIdx.x;
    if (i < n) atomicAdd(&g_count[seg[i]], 1);
    int stride = gridDim.x * blockDim.x;
    for (int j = i; j < out_n; j += stride) out[j] = 0.0f;
}
__global__ __launch_bounds__(1024) void scan_kernel(int nseg) {
    __shared__ int ssum[1024];
    int t = threadIdx.x;
    int C = (nseg + 1023) >> 10;
    int lo = t * C, hi = min(lo + C, nseg);
    int s = 0;
    for (int i = lo; i < hi; i++) s += g_count[i];
    ssum[t] = s;
    __syncthreads();
    for (int d = 1; d < 1024; d <<= 1) {
        int o = (t >= d) ? ssum[t - d] : 0;
        __syncthreads();
        ssum[t] += o;
        __syncthreads();
    }
    int pre = ssum[t] - s;
    for (int i = lo; i < hi; i++) { int c = g_count[i]; g_cursor[i] = pre; pre += c; }
}
__global__ void scatter_kernel(const int* __restrict__ seg, int n) {
    int i = blockIdx.x * blockDim.x + threadIdx.x;
    if (i < n) { int pos = atomicAdd(&g_cursor[seg[i]], 1); g_sorted[pos] = i; }
}

// ---------------- persistent warp-MMA fused MLP + fragment-space segment max ----------------

__global__ __launch_bounds__(256, 2) void fused_mlp_segmax_mma(
    const float* __restrict__ X, const int* __restrict__ seg,
    const float* __restrict__ W1, const float* __restrict__ b1,
    const float* __restrict__ W2, const float* __restrict__ b2,
    unsigned* __restrict__ out, int n)
{
    extern __shared__ char smem[];
    const uint32_t su = smem_u32_of(smem);
    int t = threadIdx.x;
    int wid = t >> 5, lane = t & 31;
    int g = lane >> 2, tig = lane & 3;
    int m0 = wid * 16;

    float* sb1 = (float*)(smem + OFF_SB1);
    float* sb2 = (float*)(smem + OFF_SB2);

    // ---- stage fp16 weights once per (persistent) CTA ----
    #pragma unroll
    for (int i = 0; i < 8; i++) {                 // B1: 64n x 32k
        int e = i * 256 + t, nn = e & 63, k = e >> 6;
        *(__half*)(smem + OFF_B1 + nn * B1S + k * 2) = __float2half_rn(W1[k * HD + nn]);
    }
    #pragma unroll
    for (int i = 0; i < 32; i++) {                // B2: 128n x 64k
        int e = i * 256 + t, nn = e & 127, k = e >> 7;
        *(__half*)(smem + OFF_B2 + nn * HS + k * 2) = __float2half_rn(W2[k * ED + nn]);
    }
    if (t < HD) sb1[t] = b1[t];
    if (t < ED) sb2[t] = b2[t];
    __syncthreads();   // the only block barrier

    int b_nrow = (lane & 7) + ((lane >> 4) << 3);
    int b_koff = ((lane >> 3) & 1) * 16;

    // ---- hoist tile-invariant B1 fragments into registers (32 regs) ----
    uint32_t B1f[2][4][4];
    #pragma unroll
    for (int ks = 0; ks < 2; ks++)
        #pragma unroll
        for (int ntp = 0; ntp < 4; ntp++)
            ldsm4(B1f[ks][ntp],
                  su + (uint32_t)(OFF_B1 + (16 * ntp + b_nrow) * B1S + ks * 32 + b_koff));

    int tiles_total = (n + MT - 1) >> 7;
    int stride = gridDim.x;

    // ---- initial gather prefetch: this thread's own A-fragment elements ----
    // rows m0+g and m0+g+8; float2 at element offsets tig + 4c (c=0..3).
    float2 xf0[4], xf1[4];
    int pseg = 0;
    if (blockIdx.x < tiles_total) {
        int base0 = blockIdx.x << 7;
        int p0 = g_sorted[min(base0 + m0 + g, n - 1)];
        int p1 = g_sorted[min(base0 + m0 + g + 8, n - 1)];
        const float2* r0 = reinterpret_cast<const float2*>(X + (size_t)p0 * FD);
        const float2* r1 = reinterpret_cast<const float2*>(X + (size_t)p1 * FD);
        #pragma unroll
        for (int c = 0; c < 4; c++) {
            xf0[c] = __ldg(r0 + tig + 4 * c);
            xf1[c] = __ldg(r1 + tig + 4 * c);
        }
        int ps = g_sorted[min(base0 + m0 + lane, n - 1)];
        pseg = __ldg(seg + ps);
    }

    for (int tile = blockIdx.x; tile < tiles_total; tile += stride) {

        // ---- this tile's seg ids in registers; run-boundary mask ----
        int segv = pseg;                           // lane l (<16): seg of row m0+l
        int prev = __shfl_up_sync(0xffffffffu, segv, 1);
        unsigned bmask = __ballot_sync(0xffffffffu,
                                       (lane > 0) && (lane < 16) && (segv != prev));

        // ---- build GEMM1 A-fragments directly from prefetched registers ----
        // ah[ks] = {row g k-lo, row g+8 k-lo, row g k-hi, row g+8 k-hi}
        uint32_t ahx[2][4];
        #pragma unroll
        for (int ks = 0; ks < 2; ks++) {
            ahx[ks][0] = pack2(xf0[2 * ks].x,     xf0[2 * ks].y);
            ahx[ks][1] = pack2(xf1[2 * ks].x,     xf1[2 * ks].y);
            ahx[ks][2] = pack2(xf0[2 * ks + 1].x, xf0[2 * ks + 1].y);
            ahx[ks][3] = pack2(xf1[2 * ks + 1].x, xf1[2 * ks + 1].y);
        }

        // ---- issue next tile's gather (latency hidden under GEMMs + epilogue) ----
        {
            int tile1 = tile + stride;
            bool more = tile1 < tiles_total;
            int base1 = tile1 << 7;
            int i0 = more ? min(base1 + m0 + g, n - 1) : 0;
            int i1 = more ? min(base1 + m0 + g + 8, n - 1) : 0;
            int p0 = g_sorted[i0];
            int p1 = g_sorted[i1];
            const float2* r0 = reinterpret_cast<const float2*>(X + (size_t)p0 * FD);
            const float2* r1 = reinterpret_cast<const float2*>(X + (size_t)p1 * FD);
            #pragma unroll
            for (int c = 0; c < 4; c++) {
                xf0[c] = __ldg(r0 + tig + 4 * c);
                xf1[c] = __ldg(r1 + tig + 4 * c);
            }
            int is = more ? min(base1 + m0 + lane, n - 1) : 0;
            int ps = g_sorted[is];
            pseg = __ldg(seg + ps);
        }

        // ================ GEMM1: H = relu(X @ W1 + b1), 16m x 64n ================
        float acc1[8][4];
        #pragma unroll
        for (int nt = 0; nt < 8; nt++)
            #pragma unroll
            for (int c = 0; c < 4; c++) acc1[nt][c] = 0.f;

        #pragma unroll
        for (int ks = 0; ks < 2; ks++)
            #pragma unroll
            for (int ntp = 0; ntp < 4; ntp++) {
                mma16816(acc1[2 * ntp],     ahx[ks], B1f[ks][ntp][0], B1f[ks][ntp][1]);
                mma16816(acc1[2 * ntp + 1], ahx[ks], B1f[ks][ntp][2], B1f[ks][ntp][3]);
            }

        // ---- H: bias+ReLU+fp16 in registers; GEMM1 C-frags == GEMM2 A-frags ----
        uint32_t Ah[4][4];
        #pragma unroll
        for (int kb = 0; kb < 4; kb++) {
            #pragma unroll
            for (int h = 0; h < 2; h++) {
                int nt = 2 * kb + h;
                int j = 8 * nt + 2 * tig;
                float bb0 = sb1[j], bb1 = sb1[j + 1];
                Ah[kb][2 * h] =
                    pack2(fmaxf(acc1[nt][0] + bb0, 0.f), fmaxf(acc1[nt][1] + bb1, 0.f));
                Ah[kb][2 * h + 1] =
                    pack2(fmaxf(acc1[nt][2] + bb0, 0.f), fmaxf(acc1[nt][3] + bb1, 0.f));
            }
        }

        // ================ GEMM2 (two 64-col halves) + fragment-space epilogue ================
        #pragma unroll 1
        for (int nh = 0; nh < 2; nh++) {
            float acc[8][4];
            #pragma unroll
            for (int nt = 0; nt < 8; nt++)
                #pragma unroll
                for (int c = 0; c < 4; c++) acc[nt][c] = 0.f;

            #pragma unroll
            for (int ks = 0; ks < 4; ks++)
                #pragma unroll
                for (int ntp = 0; ntp < 4; ntp++) {
                    uint32_t bh[4];
                    ldsm4(bh, su + (uint32_t)(OFF_B2 + (64 * nh + 16 * ntp + b_nrow) * HS + ks * 32 + b_koff));
                    mma16816(acc[2 * ntp],     Ah[ks], bh[0], bh[1]);
                    mma16816(acc[2 * ntp + 1], Ah[ks], bh[2], bh[3]);
                }

            // bias + ReLU in place
            #pragma unroll
            for (int nt = 0; nt < 8; nt++) {
                int j = 64 * nh + 8 * nt + 2 * tig;
                float bb0 = sb2[j], bb1 = sb2[j + 1];
                acc[nt][0] = fmaxf(acc[nt][0] + bb0, 0.f);
                acc[nt][1] = fmaxf(acc[nt][1] + bb1, 0.f);
                acc[nt][2] = fmaxf(acc[nt][2] + bb0, 0.f);
                acc[nt][3] = fmaxf(acc[nt][3] + bb1, 0.f);
            }

            // per-run shuffle-butterfly max over rows, atomics from lane g==nt
            int start = 0;
            while (start < 16) {
                unsigned hi = bmask & (0xFFFFFFFFu << (start + 1));
                int nb = hi ? (__ffs(hi) - 1) : 16;
                int rseg = __shfl_sync(0xffffffffu, segv, start);
                bool inLo = (g >= start) && (g < nb);         // row m0+g
                bool inHi = (g + 8 >= start) && (g + 8 < nb); // row m0+g+8
                float va0 = 0.f, va1 = 0.f;
                #pragma unroll
                for (int nt = 0; nt < 8; nt++) {
                    float a0 = fmaxf(inLo ? acc[nt][0] : 0.f, inHi ? acc[nt][2] : 0.f);
                    float a1 = fmaxf(inLo ? acc[nt][1] : 0.f, inHi ? acc[nt][3] : 0.f);
                    a0 = fmaxf(a0, __shfl_xor_sync(0xffffffffu, a0, 4));
                    a1 = fmaxf(a1, __shfl_xor_sync(0xffffffffu, a1, 4));
                    a0 = fmaxf(a0, __shfl_xor_sync(0xffffffffu, a0, 8));
                    a1 = fmaxf(a1, __shfl_xor_sync(0xffffffffu, a1, 8));
                    a0 = fmaxf(a0, __shfl_xor_sync(0xffffffffu, a0, 16));
                    a1 = fmaxf(a1, __shfl_xor_sync(0xffffffffu, a1, 16));
                    if (g == nt) { va0 = a0; va1 = a1; }
                }
                unsigned* ob = out + (size_t)rseg * ED + 64 * nh + 8 * g + 2 * tig;
                unsigned u0 = __float_as_uint(va0);   // >=0: bit order == fp order
                unsigned u1 = __float_as_uint(va1);
                if (u0) atomicMax(ob, u0);
                if (u1) atomicMax(ob + 1, u1);
                start = nb;
            }
        }
    }
}

extern "C" void kernel_launch(void* const* d_in, const int* in_sizes, int n_in,
                              void* d_out, int out_size)
{
    const float* X   = (const float*)d_in[0];
    const int*   seg = (const int*)  d_in[1];
    const float* W1  = (const float*)d_in[2];
    const float* b1  = (const float*)d_in[3];
    const float* W2  = (const float*)d_in[4];
    const float* b2  = (const float*)d_in[5];
    float* out = (float*)d_out;

    int n = in_sizes[1];
    int nseg = out_size / ED;

    cudaFuncSetAttribute(fused_mlp_segmax_mma,
                         cudaFuncAttributeMaxDynamicSharedMemorySize, SMEM_TOTAL);

    init_counts<<<(nseg + 255) / 256, 256>>>(nseg);
    hist_zero_kernel<<<(n + 255) / 256, 256>>>(seg, n, out, out_size);
    scan_kernel<<<1, 1024>>>(nseg);
    scatter_kernel<<<(n + 255) / 256, 256>>>(seg, n);

    int tiles = (n + MT - 1) / MT;
    int grid = min(296, tiles);                   // persistent: 2 CTAs x 148 SMs
    fused_mlp_segmax_mma<<<grid, 256, SMEM_TOTAL>>>(X, seg, W1, b1, W2, b2, (unsigned*)out, n);
}